// round 9
// baseline (speedup 1.0000x reference)
#include <cuda_runtime.h>
#include <cuda_bf16.h>
#include <cstdint>
#include <math.h>

// ---------------------------------------------------------------------------
// GCNGraph (sm_100, legacy mma.sync).
//   L1/L2: h = relu(adj @ (h@W) + b)   big GEMM bf16 m16n8k16 + ldmatrix
//   L3 folded: mean_s(adj@hW3+b3) = R@hW3/cnt+b3, fp32 path
//   MLP tail + sigmoid.
// R9: big GEMM tile 128x256 (warp 64x64), MMA/LDSM 2.67, zero_bufs merged.
// ---------------------------------------------------------------------------

#define NN      8192
#define HF      512
#define GRAPHS  64

__device__ __nv_bfloat16 g_adjB[(size_t)NN * NN];  // bf16 adjacency (128MB)
__device__ __nv_bfloat16 g_bufAb[NN * HF];         // h@W bf16 (layers 1-2)
__device__ float g_bufA[NN * HF];                  // h@W3 fp32 (layer 3)
__device__ float g_bufB[NN * HF];                  // layer output h
__device__ float g_R[GRAPHS * NN];                 // segment rowsums of adj
__device__ float g_G[GRAPHS * HF];                 // segment sums layer-3

__device__ __forceinline__ uint32_t f2tf32(float x) {
    uint32_t r;
    asm("cvt.rna.tf32.f32 %0, %1;" : "=r"(r) : "f"(x));
    return r;
}
__device__ __forceinline__ uint32_t smem_u32(const void* p) {
    uint32_t a;
    asm("{ .reg .u64 t; cvta.to.shared.u64 t, %1; cvt.u32.u64 %0, t; }" : "=r"(a) : "l"(p));
    return a;
}

// ===================== bf16 big GEMM (adj @ hW) =============================
// C[8192,512] = Abf[8192,8192] @ Bbf[8192,512] (+bias, relu), fp32 accum.
// Tile 128x256x32, 8 warps (2m x 4n), warp tile 64x64.

#define NSTG 4
#define BBM 128
#define BBN 256
#define BBK 32
#define A_RSTRIDE 80    // bytes per A smem row (64 data + 16 pad)
#define B_RSTRIDE 528   // bytes per B smem row (512 data + 16 pad)
#define A_BYTES (BBM * A_RSTRIDE)        // 10240
#define B_BYTES (BBK * B_RSTRIDE)        // 16896
#define STAGE_BYTES (A_BYTES + B_BYTES)  // 27136
#define BIG_SMEM (NSTG * STAGE_BYTES)    // 108544

__device__ __forceinline__ void ldmA(uint32_t a[4], uint32_t addr) {
    asm volatile("ldmatrix.sync.aligned.m8n8.x4.shared.b16 {%0,%1,%2,%3}, [%4];"
                 : "=r"(a[0]), "=r"(a[1]), "=r"(a[2]), "=r"(a[3]) : "r"(addr));
}
__device__ __forceinline__ void ldmB(uint32_t b[2], uint32_t addr) {
    asm volatile("ldmatrix.sync.aligned.m8n8.x2.trans.shared.b16 {%0,%1}, [%2];"
                 : "=r"(b[0]), "=r"(b[1]) : "r"(addr));
}
__device__ __forceinline__ void mma_bf16(float* c, const uint32_t* a, const uint32_t* b) {
    asm volatile(
        "mma.sync.aligned.m16n8k16.row.col.f32.bf16.bf16.f32 "
        "{%0,%1,%2,%3}, {%4,%5,%6,%7}, {%8,%9}, {%0,%1,%2,%3};"
        : "+f"(c[0]), "+f"(c[1]), "+f"(c[2]), "+f"(c[3])
        : "r"(a[0]), "r"(a[1]), "r"(a[2]), "r"(a[3]), "r"(b[0]), "r"(b[1]));
}

__global__ void __launch_bounds__(256, 1)
big_gemm_bf16(const __nv_bfloat16* __restrict__ A, const __nv_bfloat16* __restrict__ B,
              float* __restrict__ C, const float* __restrict__ bias, int relu)
{
    extern __shared__ char smem[];
    const uint32_t sbase = smem_u32(smem);

    const int tid  = threadIdx.x;
    const int warp = tid >> 5;
    const int lane = tid & 31;
    const int bm = blockIdx.y * BBM;
    const int bn = blockIdx.x * BBN;
    const int wm = (warp >> 2) * 64;       // 2 m-warps
    const int wn = (warp & 3) * 64;        // 4 n-warps
    const int g  = lane >> 2;
    const int q  = lane & 3;
    const int nk = NN / BBK;   // 256

    float acc[4][8][4];
    #pragma unroll
    for (int i = 0; i < 4; i++)
        #pragma unroll
        for (int j = 0; j < 8; j++)
            #pragma unroll
            for (int r = 0; r < 4; r++) acc[i][j][r] = 0.f;

    // cp.async: A 512 chunks (2/thread), B 1024 chunks (4/thread), 16B each
    auto issue = [&](int slot, int k0) {
        const uint32_t ab = sbase + slot * STAGE_BYTES;
        const uint32_t bb = ab + A_BYTES;
        #pragma unroll
        for (int p = 0; p < 2; p++) {
            const int c = tid + 256 * p;
            const int arow = c >> 2, ac = c & 3;            // 128 rows x 4 chunks
            asm volatile("cp.async.cg.shared.global [%0], [%1], 16;" ::
                "r"(ab + (uint32_t)(arow * A_RSTRIDE + ac * 16)),
                "l"(A + (size_t)(bm + arow) * NN + k0 + ac * 8));
        }
        #pragma unroll
        for (int p = 0; p < 4; p++) {
            const int c = tid + 256 * p;
            const int brow = c >> 5, bc = c & 31;           // 32 rows x 32 chunks
            asm volatile("cp.async.cg.shared.global [%0], [%1], 16;" ::
                "r"(bb + (uint32_t)(brow * B_RSTRIDE + bc * 16)),
                "l"(B + (size_t)(k0 + brow) * HF + bn + bc * 8));
        }
        asm volatile("cp.async.commit_group;" ::: "memory");
    };

    issue(0, 0);
    issue(1, BBK);
    issue(2, 2 * BBK);

    const int a_lrow = lane & 15;
    const int a_lkb  = (lane >> 4) * 8;
    const int b_lrow = lane & 15;

    for (int t = 0; t < nk; t++) {
        asm volatile("cp.async.wait_group 2;" ::: "memory");
        __syncthreads();
        if (t + 3 < nk) issue((t + 3) & 3, (t + 3) * BBK);

        const uint32_t ab = sbase + (t & 3) * STAGE_BYTES;
        const uint32_t bb = ab + A_BYTES;

        #pragma unroll
        for (int kk = 0; kk < BBK; kk += 16) {
            uint32_t af[4][4], bf[8][2];
            #pragma unroll
            for (int i = 0; i < 4; i++)
                ldmA(af[i], ab + (uint32_t)((wm + i * 16 + a_lrow) * A_RSTRIDE
                                            + (kk + a_lkb) * 2));
            #pragma unroll
            for (int j = 0; j < 8; j++)
                ldmB(bf[j], bb + (uint32_t)((kk + b_lrow) * B_RSTRIDE
                                            + (wn + j * 8) * 2));
            #pragma unroll
            for (int i = 0; i < 4; i++)
                #pragma unroll
                for (int j = 0; j < 8; j++)
                    mma_bf16(acc[i][j], af[i], bf[j]);
        }
    }

    // epilogue: bias + relu -> fp32 C
    #pragma unroll
    for (int i = 0; i < 4; i++) {
        #pragma unroll
        for (int j = 0; j < 8; j++) {
            const int row = bm + wm + i * 16 + g;
            const int col = bn + wn + j * 8 + 2 * q;
            const float bv0 = bias[col], bv1 = bias[col + 1];
            float v0 = acc[i][j][0] + bv0;
            float v1 = acc[i][j][1] + bv1;
            float v2 = acc[i][j][2] + bv0;
            float v3 = acc[i][j][3] + bv1;
            if (relu) {
                v0 = fmaxf(v0, 0.f); v1 = fmaxf(v1, 0.f);
                v2 = fmaxf(v2, 0.f); v3 = fmaxf(v3, 0.f);
            }
            *(float2*)(C + (size_t)row * HF + col)       = make_float2(v0, v1);
            *(float2*)(C + (size_t)(row + 8) * HF + col) = make_float2(v2, v3);
        }
    }
}

// ================== small SIMT tf32 GEMM (H @ W) ===========================
__device__ __forceinline__ void mma_frag(float* c, const uint32_t* a, const uint32_t* b) {
    asm volatile(
        "mma.sync.aligned.m16n8k8.row.col.f32.tf32.tf32.f32 "
        "{%0,%1,%2,%3}, {%4,%5,%6,%7}, {%8,%9}, {%0,%1,%2,%3};"
        : "+f"(c[0]), "+f"(c[1]), "+f"(c[2]), "+f"(c[3])
        : "r"(a[0]), "r"(a[1]), "r"(a[2]), "r"(a[3]), "r"(b[0]), "r"(b[1]));
}

#define BM 128
#define BN 128
#define BK 16
#define NTHREADS 256

template <int OUT_BF16>
__global__ void __launch_bounds__(NTHREADS)
gemm_small(const float* __restrict__ A, const float* __restrict__ B,
           float* __restrict__ Cf, __nv_bfloat16* __restrict__ Cb,
           int M, int N, int K)
{
    __shared__ uint32_t As[2][BM][BK + 4];
    __shared__ uint32_t Bs[2][BK][BN + 8];

    const int bm = blockIdx.y * BM;
    const int bn = blockIdx.x * BN;
    const int tid  = threadIdx.x;
    const int warp = tid >> 5;
    const int lane = tid & 31;
    const int wm = (warp >> 2) * 64;
    const int wn = (warp & 3) * 32;
    const int g  = lane >> 2;
    const int q  = lane & 3;

    float acc[4][4][4];
    #pragma unroll
    for (int i = 0; i < 4; i++)
        #pragma unroll
        for (int j = 0; j < 4; j++)
            #pragma unroll
            for (int r = 0; r < 4; r++) acc[i][j][r] = 0.f;

    const int arow = tid >> 2;
    const int acol = (tid & 3) * 4;
    const int brow = tid >> 5;
    const int bcol = (tid & 31) * 4;
    const int nk = K / BK;

    float4 ra0, ra1, rb0, rb1;
    ra0 = *(const float4*)(A + (size_t)(bm + arow) * K + acol);
    ra1 = *(const float4*)(A + (size_t)(bm + arow + 64) * K + acol);
    rb0 = *(const float4*)(B + (size_t)(brow) * N + bn + bcol);
    rb1 = *(const float4*)(B + (size_t)(brow + 8) * N + bn + bcol);
    {
        uint4 u;
        u.x = f2tf32(ra0.x); u.y = f2tf32(ra0.y); u.z = f2tf32(ra0.z); u.w = f2tf32(ra0.w);
        *(uint4*)&As[0][arow][acol] = u;
        u.x = f2tf32(ra1.x); u.y = f2tf32(ra1.y); u.z = f2tf32(ra1.z); u.w = f2tf32(ra1.w);
        *(uint4*)&As[0][arow + 64][acol] = u;
        u.x = f2tf32(rb0.x); u.y = f2tf32(rb0.y); u.z = f2tf32(rb0.z); u.w = f2tf32(rb0.w);
        *(uint4*)&Bs[0][brow][bcol] = u;
        u.x = f2tf32(rb1.x); u.y = f2tf32(rb1.y); u.z = f2tf32(rb1.z); u.w = f2tf32(rb1.w);
        *(uint4*)&Bs[0][brow + 8][bcol] = u;
    }
    __syncthreads();

    for (int t = 0; t < nk; t++) {
        const int cur = t & 1;
        const int nxt = cur ^ 1;
        const bool more = (t + 1 < nk);
        if (more) {
            const int k0 = (t + 1) * BK;
            ra0 = *(const float4*)(A + (size_t)(bm + arow) * K + k0 + acol);
            ra1 = *(const float4*)(A + (size_t)(bm + arow + 64) * K + k0 + acol);
            rb0 = *(const float4*)(B + (size_t)(k0 + brow) * N + bn + bcol);
            rb1 = *(const float4*)(B + (size_t)(k0 + brow + 8) * N + bn + bcol);
        }
        #pragma unroll
        for (int kk = 0; kk < BK; kk += 8) {
            uint32_t af[4][4], bf[4][2];
            #pragma unroll
            for (int i = 0; i < 4; i++) {
                const int r0 = wm + i * 16 + g;
                af[i][0] = As[cur][r0][kk + q];
                af[i][1] = As[cur][r0 + 8][kk + q];
                af[i][2] = As[cur][r0][kk + q + 4];
                af[i][3] = As[cur][r0 + 8][kk + q + 4];
            }
            #pragma unroll
            for (int j = 0; j < 4; j++) {
                const int c0 = wn + j * 8 + g;
                bf[j][0] = Bs[cur][kk + q][c0];
                bf[j][1] = Bs[cur][kk + q + 4][c0];
            }
            #pragma unroll
            for (int i = 0; i < 4; i++)
                #pragma unroll
                for (int j = 0; j < 4; j++)
                    mma_frag(acc[i][j], af[i], bf[j]);
        }
        if (more) {
            uint4 u;
            u.x = f2tf32(ra0.x); u.y = f2tf32(ra0.y); u.z = f2tf32(ra0.z); u.w = f2tf32(ra0.w);
            *(uint4*)&As[nxt][arow][acol] = u;
            u.x = f2tf32(ra1.x); u.y = f2tf32(ra1.y); u.z = f2tf32(ra1.z); u.w = f2tf32(ra1.w);
            *(uint4*)&As[nxt][arow + 64][acol] = u;
            u.x = f2tf32(rb0.x); u.y = f2tf32(rb0.y); u.z = f2tf32(rb0.z); u.w = f2tf32(rb0.w);
            *(uint4*)&Bs[nxt][brow][bcol] = u;
            u.x = f2tf32(rb1.x); u.y = f2tf32(rb1.y); u.z = f2tf32(rb1.z); u.w = f2tf32(rb1.w);
            *(uint4*)&Bs[nxt][brow + 8][bcol] = u;
        }
        __syncthreads();
    }

    #pragma unroll
    for (int i = 0; i < 4; i++) {
        #pragma unroll
        for (int j = 0; j < 4; j++) {
            const int row = bm + wm + i * 16 + g;
            const int col = bn + wn + j * 8 + 2 * q;
            if (OUT_BF16) {
                *(__nv_bfloat162*)(Cb + (size_t)row * N + col) =
                    __floats2bfloat162_rn(acc[i][j][0], acc[i][j][1]);
                *(__nv_bfloat162*)(Cb + (size_t)(row + 8) * N + col) =
                    __floats2bfloat162_rn(acc[i][j][2], acc[i][j][3]);
            } else {
                *(float2*)(Cf + (size_t)row * N + col) =
                    make_float2(acc[i][j][0], acc[i][j][1]);
                *(float2*)(Cf + (size_t)(row + 8) * N + col) =
                    make_float2(acc[i][j][2], acc[i][j][3]);
            }
        }
    }
}

// =============================== helpers ====================================

// Fused: adjB = bf16(adj) AND R[s][col] += segment rowsums (fp32).
#define SR_CHUNK 256

__global__ void __launch_bounds__(256)
segrow_conv(const float* __restrict__ adj, const int* __restrict__ seg,
            __nv_bfloat16* __restrict__ adjB, float* __restrict__ R)
{
    const int col = (blockIdx.x * 256 + threadIdx.x) * 4;
    const int r0  = blockIdx.y * SR_CHUNK;
    const int r1  = r0 + SR_CHUNK;

    float4 acc = make_float4(0.f, 0.f, 0.f, 0.f);
    int cur = seg[r0];

    #pragma unroll 4
    for (int i = r0; i < r1; i++) {
        const int s = __ldg(&seg[i]);
        if (s != cur) {
            atomicAdd(&R[(size_t)cur * NN + col],     acc.x);
            atomicAdd(&R[(size_t)cur * NN + col + 1], acc.y);
            atomicAdd(&R[(size_t)cur * NN + col + 2], acc.z);
            atomicAdd(&R[(size_t)cur * NN + col + 3], acc.w);
            acc = make_float4(0.f, 0.f, 0.f, 0.f);
            cur = s;
        }
        const float4 v = *(const float4*)(adj + (size_t)i * NN + col);
        acc.x += v.x; acc.y += v.y; acc.z += v.z; acc.w += v.w;
        __nv_bfloat162 o01 = __floats2bfloat162_rn(v.x, v.y);
        __nv_bfloat162 o23 = __floats2bfloat162_rn(v.z, v.w);
        uint2 o;
        o.x = *(uint32_t*)&o01;
        o.y = *(uint32_t*)&o23;
        *(uint2*)(adjB + (size_t)i * NN + col) = o;
    }
    atomicAdd(&R[(size_t)cur * NN + col],     acc.x);
    atomicAdd(&R[(size_t)cur * NN + col + 1], acc.y);
    atomicAdd(&R[(size_t)cur * NN + col + 2], acc.z);
    atomicAdd(&R[(size_t)cur * NN + col + 3], acc.w);
}

// one launch zeroes both R and G (also steers ncu -s 5 onto big_gemm)
__global__ void zero_all(float* __restrict__ R, float* __restrict__ G) {
    const int i = blockIdx.x * blockDim.x + threadIdx.x;
    if (i < GRAPHS * NN) R[i] = 0.f;
    if (i < GRAPHS * HF) G[i] = 0.f;
}

// G[64,512] += R[64,8192] @ H[8192,512]  (fp32 SIMT, k-split with atomics)
__global__ void __launch_bounds__(256)
tiny_gemm(const float* __restrict__ R, const float* __restrict__ H,
          float* __restrict__ G)
{
    __shared__ float sA[64][33];
    __shared__ float sB[32][132];
    const int tid = threadIdx.x;
    const int bn = blockIdx.x * 128;
    const int k0 = blockIdx.y * 512;
    const int row0 = (tid >> 5) * 8;
    const int col0 = (tid & 31) * 4;

    float acc[8][4];
    #pragma unroll
    for (int r = 0; r < 8; r++)
        #pragma unroll
        for (int c = 0; c < 4; c++) acc[r][c] = 0.f;

    for (int kt = 0; kt < 512; kt += 32) {
        const int k = k0 + kt;
        #pragma unroll
        for (int i = 0; i < 8; i++) {
            const int e = tid + 256 * i;
            sA[e >> 5][e & 31] = R[(size_t)(e >> 5) * NN + k + (e & 31)];
        }
        #pragma unroll
        for (int i = 0; i < 16; i++) {
            const int e = tid + 256 * i;
            sB[e >> 7][e & 127] = H[(size_t)(k + (e >> 7)) * HF + bn + (e & 127)];
        }
        __syncthreads();
        #pragma unroll
        for (int kk = 0; kk < 32; kk++) {
            const float4 b4 = *(const float4*)&sB[kk][col0];
            #pragma unroll
            for (int r = 0; r < 8; r++) {
                const float a = sA[row0 + r][kk];
                acc[r][0] += a * b4.x;
                acc[r][1] += a * b4.y;
                acc[r][2] += a * b4.z;
                acc[r][3] += a * b4.w;
            }
        }
        __syncthreads();
    }
    #pragma unroll
    for (int r = 0; r < 8; r++)
        #pragma unroll
        for (int c = 0; c < 4; c++)
            atomicAdd(&G[(row0 + r) * HF + bn + col0 + c], acc[r][c]);
}

// mean + b3 + MLP (512->16->8->1) + sigmoid. one block, 1024 threads.
__global__ void mlp_tail(const float* __restrict__ G, const int* __restrict__ seg,
                         const float* __restrict__ b3,
                         const float* __restrict__ D1, const float* __restrict__ db1,
                         const float* __restrict__ D2, const float* __restrict__ db2,
                         const float* __restrict__ D3, const float* __restrict__ db3,
                         float* __restrict__ out)
{
    __shared__ int   cnt[GRAPHS];
    __shared__ float s1[GRAPHS][16];
    __shared__ float s2[GRAPHS][8];
    const int tid = threadIdx.x;

    if (tid < GRAPHS) cnt[tid] = 0;
    __syncthreads();
    for (int n = tid; n < NN; n += 1024) atomicAdd(&cnt[seg[n]], 1);
    __syncthreads();

    {
        const int gph = tid >> 4, j = tid & 15;
        const float inv = 1.f / (float)max(cnt[gph], 1);
        float acc = 0.f;
        const float* grow = G + gph * HF;
        for (int k = 0; k < HF; k++)
            acc += (grow[k] * inv + b3[k]) * D1[k * 16 + j];
        s1[gph][j] = fmaxf(acc + db1[j], 0.f);
    }
    __syncthreads();
    if (tid < 512) {
        const int gph = tid >> 3, j = tid & 7;
        float acc = 0.f;
        for (int k = 0; k < 16; k++) acc += s1[gph][k] * D2[k * 8 + j];
        s2[gph][j] = fmaxf(acc + db2[j], 0.f);
    }
    __syncthreads();
    if (tid < GRAPHS) {
        float acc = 0.f;
        for (int k = 0; k < 8; k++) acc += s2[tid][k] * D3[k];
        out[tid] = 1.f / (1.f + expf(-(acc + db3[0])));
    }
}

// ================================= host =====================================

extern "C" void kernel_launch(void* const* d_in, const int* in_sizes, int n_in,
                              void* d_out, int out_size)
{
    const float* X   = (const float*)d_in[0];
    const float* adj = (const float*)d_in[1];
    const int*   seg = (const int*)d_in[2];
    const int base = n_in - 12;
    const float* W1  = (const float*)d_in[base + 0];
    const float* b1  = (const float*)d_in[base + 1];
    const float* W2  = (const float*)d_in[base + 2];
    const float* b2  = (const float*)d_in[base + 3];
    const float* W3  = (const float*)d_in[base + 4];
    const float* b3  = (const float*)d_in[base + 5];
    const float* D1  = (const float*)d_in[base + 6];
    const float* db1 = (const float*)d_in[base + 7];
    const float* D2  = (const float*)d_in[base + 8];
    const float* db2 = (const float*)d_in[base + 9];
    const float* D3  = (const float*)d_in[base + 10];
    const float* db3 = (const float*)d_in[base + 11];
    float* out = (float*)d_out;

    __nv_bfloat16 *adjB, *bufAb;
    float *bufA, *bufB, *R, *G;
    cudaGetSymbolAddress((void**)&adjB, g_adjB);
    cudaGetSymbolAddress((void**)&bufAb, g_bufAb);
    cudaGetSymbolAddress((void**)&bufA, g_bufA);
    cudaGetSymbolAddress((void**)&bufB, g_bufB);
    cudaGetSymbolAddress((void**)&R, g_R);
    cudaGetSymbolAddress((void**)&G, g_G);

    static bool attr_set = false;
    if (!attr_set) {
        cudaFuncSetAttribute(big_gemm_bf16, cudaFuncAttributeMaxDynamicSharedMemorySize, BIG_SMEM);
        attr_set = true;
    }

    const dim3 blk(NTHREADS);
    const dim3 sgrd(HF / BN, NN / BM);    // (4, 64)
    const dim3 bgrd(HF / BBN, NN / BBM);  // (2, 64)

    // prep
    zero_all<<<(GRAPHS * NN + 255) / 256, 256>>>(R, G);
    segrow_conv<<<dim3(NN / 1024, NN / SR_CHUNK), 256>>>(adj, seg, adjB, R);

    // layer 1
    gemm_small<1><<<sgrd, blk>>>(X, W1, nullptr, bufAb, NN, HF, 256);
    big_gemm_bf16<<<bgrd, 256, BIG_SMEM>>>(adjB, bufAb, bufB, b1, 1);
    // layer 2
    gemm_small<1><<<sgrd, blk>>>(bufB, W2, nullptr, bufAb, NN, HF, HF);
    big_gemm_bf16<<<bgrd, 256, BIG_SMEM>>>(adjB, bufAb, bufB, b2, 1);
    // layer 3 folded: hW3 (fp32), then R @ hW3
    gemm_small<0><<<sgrd, blk>>>(bufB, W3, bufA, nullptr, NN, HF, HF);
    tiny_gemm<<<dim3(HF / 128, NN / 512), 256>>>(R, bufA, G);

    // tail
    mlp_tail<<<1, 1024>>>(G, seg, b3, D1, db1, D2, db2, D3, db3, out);
}

// round 10
// speedup vs baseline: 1.0495x; 1.0495x over previous
#include <cuda_runtime.h>
#include <cuda_bf16.h>
#include <cstdint>
#include <math.h>

// ---------------------------------------------------------------------------
// GCNGraph (sm_100, legacy mma.sync).
//   L1/L2: h = relu(adj @ (h@W) + b)   big GEMM bf16 m16n8k16 + ldmatrix
//   L3 folded: mean_s(adj@hW3+b3) = R@hW3/cnt+b3, fp32 path
//   MLP tail + sigmoid.
// R10: big GEMM BBK=64 (half the barriers), ldmatrix.x4 for B, 3 stages.
// ---------------------------------------------------------------------------

#define NN      8192
#define HF      512
#define GRAPHS  64

__device__ __nv_bfloat16 g_adjB[(size_t)NN * NN];  // bf16 adjacency (128MB)
__device__ __nv_bfloat16 g_bufAb[NN * HF];         // h@W bf16 (layers 1-2)
__device__ float g_bufA[NN * HF];                  // h@W3 fp32 (layer 3)
__device__ float g_bufB[NN * HF];                  // layer output h
__device__ float g_R[GRAPHS * NN];                 // segment rowsums of adj
__device__ float g_G[GRAPHS * HF];                 // segment sums layer-3

__device__ __forceinline__ uint32_t f2tf32(float x) {
    uint32_t r;
    asm("cvt.rna.tf32.f32 %0, %1;" : "=r"(r) : "f"(x));
    return r;
}
__device__ __forceinline__ uint32_t smem_u32(const void* p) {
    uint32_t a;
    asm("{ .reg .u64 t; cvta.to.shared.u64 t, %1; cvt.u32.u64 %0, t; }" : "=r"(a) : "l"(p));
    return a;
}

// ===================== bf16 big GEMM (adj @ hW) =============================
// C[8192,512] = Abf[8192,8192] @ Bbf[8192,512] (+bias, relu), fp32 accum.
// Tile 128x256x64, 8 warps (2m x 4n), warp tile 64x64, 3-stage cp.async.

#define NSTG 3
#define BBM 128
#define BBN 256
#define BBK 64
#define A_RSTRIDE 144   // bytes per A smem row (128 data + 16 pad)
#define B_RSTRIDE 528   // bytes per B smem row (512 data + 16 pad)
#define A_BYTES (BBM * A_RSTRIDE)        // 18432
#define B_BYTES (BBK * B_RSTRIDE)        // 33792
#define STAGE_BYTES (A_BYTES + B_BYTES)  // 52224
#define BIG_SMEM (NSTG * STAGE_BYTES)    // 156672

__device__ __forceinline__ void ldmA(uint32_t a[4], uint32_t addr) {
    asm volatile("ldmatrix.sync.aligned.m8n8.x4.shared.b16 {%0,%1,%2,%3}, [%4];"
                 : "=r"(a[0]), "=r"(a[1]), "=r"(a[2]), "=r"(a[3]) : "r"(addr));
}
__device__ __forceinline__ void ldmB4(uint32_t b[4], uint32_t addr) {
    asm volatile("ldmatrix.sync.aligned.m8n8.x4.trans.shared.b16 {%0,%1,%2,%3}, [%4];"
                 : "=r"(b[0]), "=r"(b[1]), "=r"(b[2]), "=r"(b[3]) : "r"(addr));
}
__device__ __forceinline__ void mma_bf16(float* c, const uint32_t* a, const uint32_t* b) {
    asm volatile(
        "mma.sync.aligned.m16n8k16.row.col.f32.bf16.bf16.f32 "
        "{%0,%1,%2,%3}, {%4,%5,%6,%7}, {%8,%9}, {%0,%1,%2,%3};"
        : "+f"(c[0]), "+f"(c[1]), "+f"(c[2]), "+f"(c[3])
        : "r"(a[0]), "r"(a[1]), "r"(a[2]), "r"(a[3]), "r"(b[0]), "r"(b[1]));
}

__global__ void __launch_bounds__(256, 1)
big_gemm_bf16(const __nv_bfloat16* __restrict__ A, const __nv_bfloat16* __restrict__ B,
              float* __restrict__ C, const float* __restrict__ bias, int relu)
{
    extern __shared__ char smem[];
    const uint32_t sbase = smem_u32(smem);

    const int tid  = threadIdx.x;
    const int warp = tid >> 5;
    const int lane = tid & 31;
    const int bm = blockIdx.y * BBM;
    const int bn = blockIdx.x * BBN;
    const int wm = (warp >> 2) * 64;       // 2 m-warps
    const int wn = (warp & 3) * 64;        // 4 n-warps
    const int g  = lane >> 2;
    const int q  = lane & 3;
    const int nk = NN / BBK;   // 128

    float acc[4][8][4];
    #pragma unroll
    for (int i = 0; i < 4; i++)
        #pragma unroll
        for (int j = 0; j < 8; j++)
            #pragma unroll
            for (int r = 0; r < 4; r++) acc[i][j][r] = 0.f;

    // cp.async: A 1024 chunks (4/thread), B 2048 chunks (8/thread), 16B each
    auto issue = [&](int slot, int k0) {
        const uint32_t ab = sbase + slot * STAGE_BYTES;
        const uint32_t bb = ab + A_BYTES;
        #pragma unroll
        for (int p = 0; p < 4; p++) {
            const int c = tid + 256 * p;
            const int arow = c >> 3, ac = c & 7;            // 128 rows x 8 chunks
            asm volatile("cp.async.cg.shared.global [%0], [%1], 16;" ::
                "r"(ab + (uint32_t)(arow * A_RSTRIDE + ac * 16)),
                "l"(A + (size_t)(bm + arow) * NN + k0 + ac * 8));
        }
        #pragma unroll
        for (int p = 0; p < 8; p++) {
            const int c = tid + 256 * p;
            const int brow = c >> 5, bc = c & 31;           // 64 rows x 32 chunks
            asm volatile("cp.async.cg.shared.global [%0], [%1], 16;" ::
                "r"(bb + (uint32_t)(brow * B_RSTRIDE + bc * 16)),
                "l"(B + (size_t)(k0 + brow) * HF + bn + bc * 8));
        }
        asm volatile("cp.async.commit_group;" ::: "memory");
    };

    issue(0, 0);
    issue(1, BBK);

    // ldmatrix lane-address components
    const int a_lrow = lane & 15;            // A: row within 16
    const int a_lkb  = (lane >> 4) * 8;      // A: k byte-block (0 or 8)
    const int b_m    = lane >> 3;            // B x4: matrix id 0..3
    const int b_krow = (b_m & 1) * 8 + (lane & 7);  // k row within 16
    const int b_ncol = (b_m >> 1) * 8;               // n sub-block (0 or 8)

    int slot = 0;
    for (int t = 0; t < nk; t++) {
        asm volatile("cp.async.wait_group 1;" ::: "memory");
        __syncthreads();
        if (t + 2 < nk) {
            int ns = slot + 2; if (ns >= NSTG) ns -= NSTG;
            issue(ns, (t + 2) * BBK);
        }

        const uint32_t ab = sbase + slot * STAGE_BYTES;
        const uint32_t bb = ab + A_BYTES;

        #pragma unroll
        for (int kk = 0; kk < BBK; kk += 16) {
            uint32_t af[4][4], bf[4][4];
            #pragma unroll
            for (int i = 0; i < 4; i++)
                ldmA(af[i], ab + (uint32_t)((wm + i * 16 + a_lrow) * A_RSTRIDE
                                            + (kk + a_lkb) * 2));
            #pragma unroll
            for (int j2 = 0; j2 < 4; j2++)
                ldmB4(bf[j2], bb + (uint32_t)((kk + b_krow) * B_RSTRIDE
                                              + (wn + j2 * 16 + b_ncol) * 2));
            #pragma unroll
            for (int i = 0; i < 4; i++)
                #pragma unroll
                for (int j2 = 0; j2 < 4; j2++) {
                    mma_bf16(acc[i][j2 * 2],     af[i], &bf[j2][0]);
                    mma_bf16(acc[i][j2 * 2 + 1], af[i], &bf[j2][2]);
                }
        }
        if (++slot >= NSTG) slot = 0;
    }

    // epilogue: bias + relu -> fp32 C
    #pragma unroll
    for (int i = 0; i < 4; i++) {
        #pragma unroll
        for (int j = 0; j < 8; j++) {
            const int row = bm + wm + i * 16 + g;
            const int col = bn + wn + j * 8 + 2 * q;
            const float bv0 = bias[col], bv1 = bias[col + 1];
            float v0 = acc[i][j][0] + bv0;
            float v1 = acc[i][j][1] + bv1;
            float v2 = acc[i][j][2] + bv0;
            float v3 = acc[i][j][3] + bv1;
            if (relu) {
                v0 = fmaxf(v0, 0.f); v1 = fmaxf(v1, 0.f);
                v2 = fmaxf(v2, 0.f); v3 = fmaxf(v3, 0.f);
            }
            *(float2*)(C + (size_t)row * HF + col)       = make_float2(v0, v1);
            *(float2*)(C + (size_t)(row + 8) * HF + col) = make_float2(v2, v3);
        }
    }
}

// ================== small SIMT tf32 GEMM (H @ W) ===========================
__device__ __forceinline__ void mma_frag(float* c, const uint32_t* a, const uint32_t* b) {
    asm volatile(
        "mma.sync.aligned.m16n8k8.row.col.f32.tf32.tf32.f32 "
        "{%0,%1,%2,%3}, {%4,%5,%6,%7}, {%8,%9}, {%0,%1,%2,%3};"
        : "+f"(c[0]), "+f"(c[1]), "+f"(c[2]), "+f"(c[3])
        : "r"(a[0]), "r"(a[1]), "r"(a[2]), "r"(a[3]), "r"(b[0]), "r"(b[1]));
}

#define BM 128
#define BN 128
#define BK 16
#define NTHREADS 256

template <int OUT_BF16>
__global__ void __launch_bounds__(NTHREADS)
gemm_small(const float* __restrict__ A, const float* __restrict__ B,
           float* __restrict__ Cf, __nv_bfloat16* __restrict__ Cb,
           int M, int N, int K)
{
    __shared__ uint32_t As[2][BM][BK + 4];
    __shared__ uint32_t Bs[2][BK][BN + 8];

    const int bm = blockIdx.y * BM;
    const int bn = blockIdx.x * BN;
    const int tid  = threadIdx.x;
    const int warp = tid >> 5;
    const int lane = tid & 31;
    const int wm = (warp >> 2) * 64;
    const int wn = (warp & 3) * 32;
    const int g  = lane >> 2;
    const int q  = lane & 3;

    float acc[4][4][4];
    #pragma unroll
    for (int i = 0; i < 4; i++)
        #pragma unroll
        for (int j = 0; j < 4; j++)
            #pragma unroll
            for (int r = 0; r < 4; r++) acc[i][j][r] = 0.f;

    const int arow = tid >> 2;
    const int acol = (tid & 3) * 4;
    const int brow = tid >> 5;
    const int bcol = (tid & 31) * 4;
    const int nk = K / BK;

    float4 ra0, ra1, rb0, rb1;
    ra0 = *(const float4*)(A + (size_t)(bm + arow) * K + acol);
    ra1 = *(const float4*)(A + (size_t)(bm + arow + 64) * K + acol);
    rb0 = *(const float4*)(B + (size_t)(brow) * N + bn + bcol);
    rb1 = *(const float4*)(B + (size_t)(brow + 8) * N + bn + bcol);
    {
        uint4 u;
        u.x = f2tf32(ra0.x); u.y = f2tf32(ra0.y); u.z = f2tf32(ra0.z); u.w = f2tf32(ra0.w);
        *(uint4*)&As[0][arow][acol] = u;
        u.x = f2tf32(ra1.x); u.y = f2tf32(ra1.y); u.z = f2tf32(ra1.z); u.w = f2tf32(ra1.w);
        *(uint4*)&As[0][arow + 64][acol] = u;
        u.x = f2tf32(rb0.x); u.y = f2tf32(rb0.y); u.z = f2tf32(rb0.z); u.w = f2tf32(rb0.w);
        *(uint4*)&Bs[0][brow][bcol] = u;
        u.x = f2tf32(rb1.x); u.y = f2tf32(rb1.y); u.z = f2tf32(rb1.z); u.w = f2tf32(rb1.w);
        *(uint4*)&Bs[0][brow + 8][bcol] = u;
    }
    __syncthreads();

    for (int t = 0; t < nk; t++) {
        const int cur = t & 1;
        const int nxt = cur ^ 1;
        const bool more = (t + 1 < nk);
        if (more) {
            const int k0 = (t + 1) * BK;
            ra0 = *(const float4*)(A + (size_t)(bm + arow) * K + k0 + acol);
            ra1 = *(const float4*)(A + (size_t)(bm + arow + 64) * K + k0 + acol);
            rb0 = *(const float4*)(B + (size_t)(k0 + brow) * N + bn + bcol);
            rb1 = *(const float4*)(B + (size_t)(k0 + brow + 8) * N + bn + bcol);
        }
        #pragma unroll
        for (int kk = 0; kk < BK; kk += 8) {
            uint32_t af[4][4], bf[4][2];
            #pragma unroll
            for (int i = 0; i < 4; i++) {
                const int r0 = wm + i * 16 + g;
                af[i][0] = As[cur][r0][kk + q];
                af[i][1] = As[cur][r0 + 8][kk + q];
                af[i][2] = As[cur][r0][kk + q + 4];
                af[i][3] = As[cur][r0 + 8][kk + q + 4];
            }
            #pragma unroll
            for (int j = 0; j < 4; j++) {
                const int c0 = wn + j * 8 + g;
                bf[j][0] = Bs[cur][kk + q][c0];
                bf[j][1] = Bs[cur][kk + q + 4][c0];
            }
            #pragma unroll
            for (int i = 0; i < 4; i++)
                #pragma unroll
                for (int j = 0; j < 4; j++)
                    mma_frag(acc[i][j], af[i], bf[j]);
        }
        if (more) {
            uint4 u;
            u.x = f2tf32(ra0.x); u.y = f2tf32(ra0.y); u.z = f2tf32(ra0.z); u.w = f2tf32(ra0.w);
            *(uint4*)&As[nxt][arow][acol] = u;
            u.x = f2tf32(ra1.x); u.y = f2tf32(ra1.y); u.z = f2tf32(ra1.z); u.w = f2tf32(ra1.w);
            *(uint4*)&As[nxt][arow + 64][acol] = u;
            u.x = f2tf32(rb0.x); u.y = f2tf32(rb0.y); u.z = f2tf32(rb0.z); u.w = f2tf32(rb0.w);
            *(uint4*)&Bs[nxt][brow][bcol] = u;
            u.x = f2tf32(rb1.x); u.y = f2tf32(rb1.y); u.z = f2tf32(rb1.z); u.w = f2tf32(rb1.w);
            *(uint4*)&Bs[nxt][brow + 8][bcol] = u;
        }
        __syncthreads();
    }

    #pragma unroll
    for (int i = 0; i < 4; i++) {
        #pragma unroll
        for (int j = 0; j < 4; j++) {
            const int row = bm + wm + i * 16 + g;
            const int col = bn + wn + j * 8 + 2 * q;
            if (OUT_BF16) {
                *(__nv_bfloat162*)(Cb + (size_t)row * N + col) =
                    __floats2bfloat162_rn(acc[i][j][0], acc[i][j][1]);
                *(__nv_bfloat162*)(Cb + (size_t)(row + 8) * N + col) =
                    __floats2bfloat162_rn(acc[i][j][2], acc[i][j][3]);
            } else {
                *(float2*)(Cf + (size_t)row * N + col) =
                    make_float2(acc[i][j][0], acc[i][j][1]);
                *(float2*)(Cf + (size_t)(row + 8) * N + col) =
                    make_float2(acc[i][j][2], acc[i][j][3]);
            }
        }
    }
}

// =============================== helpers ====================================

// Fused: adjB = bf16(adj) AND R[s][col] += segment rowsums (fp32).
#define SR_CHUNK 256

__global__ void __launch_bounds__(256)
segrow_conv(const float* __restrict__ adj, const int* __restrict__ seg,
            __nv_bfloat16* __restrict__ adjB, float* __restrict__ R)
{
    const int col = (blockIdx.x * 256 + threadIdx.x) * 4;
    const int r0  = blockIdx.y * SR_CHUNK;
    const int r1  = r0 + SR_CHUNK;

    float4 acc = make_float4(0.f, 0.f, 0.f, 0.f);
    int cur = seg[r0];

    #pragma unroll 4
    for (int i = r0; i < r1; i++) {
        const int s = __ldg(&seg[i]);
        if (s != cur) {
            atomicAdd(&R[(size_t)cur * NN + col],     acc.x);
            atomicAdd(&R[(size_t)cur * NN + col + 1], acc.y);
            atomicAdd(&R[(size_t)cur * NN + col + 2], acc.z);
            atomicAdd(&R[(size_t)cur * NN + col + 3], acc.w);
            acc = make_float4(0.f, 0.f, 0.f, 0.f);
            cur = s;
        }
        const float4 v = *(const float4*)(adj + (size_t)i * NN + col);
        acc.x += v.x; acc.y += v.y; acc.z += v.z; acc.w += v.w;
        __nv_bfloat162 o01 = __floats2bfloat162_rn(v.x, v.y);
        __nv_bfloat162 o23 = __floats2bfloat162_rn(v.z, v.w);
        uint2 o;
        o.x = *(uint32_t*)&o01;
        o.y = *(uint32_t*)&o23;
        *(uint2*)(adjB + (size_t)i * NN + col) = o;
    }
    atomicAdd(&R[(size_t)cur * NN + col],     acc.x);
    atomicAdd(&R[(size_t)cur * NN + col + 1], acc.y);
    atomicAdd(&R[(size_t)cur * NN + col + 2], acc.z);
    atomicAdd(&R[(size_t)cur * NN + col + 3], acc.w);
}

// one launch zeroes both R and G
__global__ void zero_all(float* __restrict__ R, float* __restrict__ G) {
    const int i = blockIdx.x * blockDim.x + threadIdx.x;
    if (i < GRAPHS * NN) R[i] = 0.f;
    if (i < GRAPHS * HF) G[i] = 0.f;
}

// G[64,512] += R[64,8192] @ H[8192,512]  (fp32 SIMT, k-split with atomics)
__global__ void __launch_bounds__(256)
tiny_gemm(const float* __restrict__ R, const float* __restrict__ H,
          float* __restrict__ G)
{
    __shared__ float sA[64][33];
    __shared__ float sB[32][132];
    const int tid = threadIdx.x;
    const int bn = blockIdx.x * 128;
    const int k0 = blockIdx.y * 512;
    const int row0 = (tid >> 5) * 8;
    const int col0 = (tid & 31) * 4;

    float acc[8][4];
    #pragma unroll
    for (int r = 0; r < 8; r++)
        #pragma unroll
        for (int c = 0; c < 4; c++) acc[r][c] = 0.f;

    for (int kt = 0; kt < 512; kt += 32) {
        const int k = k0 + kt;
        #pragma unroll
        for (int i = 0; i < 8; i++) {
            const int e = tid + 256 * i;
            sA[e >> 5][e & 31] = R[(size_t)(e >> 5) * NN + k + (e & 31)];
        }
        #pragma unroll
        for (int i = 0; i < 16; i++) {
            const int e = tid + 256 * i;
            sB[e >> 7][e & 127] = H[(size_t)(k + (e >> 7)) * HF + bn + (e & 127)];
        }
        __syncthreads();
        #pragma unroll
        for (int kk = 0; kk < 32; kk++) {
            const float4 b4 = *(const float4*)&sB[kk][col0];
            #pragma unroll
            for (int r = 0; r < 8; r++) {
                const float a = sA[row0 + r][kk];
                acc[r][0] += a * b4.x;
                acc[r][1] += a * b4.y;
                acc[r][2] += a * b4.z;
                acc[r][3] += a * b4.w;
            }
        }
        __syncthreads();
    }
    #pragma unroll
    for (int r = 0; r < 8; r++)
        #pragma unroll
        for (int c = 0; c < 4; c++)
            atomicAdd(&G[(row0 + r) * HF + bn + col0 + c], acc[r][c]);
}

// mean + b3 + MLP (512->16->8->1) + sigmoid. one block, 1024 threads.
__global__ void mlp_tail(const float* __restrict__ G, const int* __restrict__ seg,
                         const float* __restrict__ b3,
                         const float* __restrict__ D1, const float* __restrict__ db1,
                         const float* __restrict__ D2, const float* __restrict__ db2,
                         const float* __restrict__ D3, const float* __restrict__ db3,
                         float* __restrict__ out)
{
    __shared__ int   cnt[GRAPHS];
    __shared__ float s1[GRAPHS][16];
    __shared__ float s2[GRAPHS][8];
    const int tid = threadIdx.x;

    if (tid < GRAPHS) cnt[tid] = 0;
    __syncthreads();
    for (int n = tid; n < NN; n += 1024) atomicAdd(&cnt[seg[n]], 1);
    __syncthreads();

    {
        const int gph = tid >> 4, j = tid & 15;
        const float inv = 1.f / (float)max(cnt[gph], 1);
        float acc = 0.f;
        const float* grow = G + gph * HF;
        for (int k = 0; k < HF; k++)
            acc += (grow[k] * inv + b3[k]) * D1[k * 16 + j];
        s1[gph][j] = fmaxf(acc + db1[j], 0.f);
    }
    __syncthreads();
    if (tid < 512) {
        const int gph = tid >> 3, j = tid & 7;
        float acc = 0.f;
        for (int k = 0; k < 16; k++) acc += s1[gph][k] * D2[k * 8 + j];
        s2[gph][j] = fmaxf(acc + db2[j], 0.f);
    }
    __syncthreads();
    if (tid < GRAPHS) {
        float acc = 0.f;
        for (int k = 0; k < 8; k++) acc += s2[tid][k] * D3[k];
        out[tid] = 1.f / (1.f + expf(-(acc + db3[0])));
    }
}

// ================================= host =====================================

extern "C" void kernel_launch(void* const* d_in, const int* in_sizes, int n_in,
                              void* d_out, int out_size)
{
    const float* X   = (const float*)d_in[0];
    const float* adj = (const float*)d_in[1];
    const int*   seg = (const int*)d_in[2];
    const int base = n_in - 12;
    const float* W1  = (const float*)d_in[base + 0];
    const float* b1  = (const float*)d_in[base + 1];
    const float* W2  = (const float*)d_in[base + 2];
    const float* b2  = (const float*)d_in[base + 3];
    const float* W3  = (const float*)d_in[base + 4];
    const float* b3  = (const float*)d_in[base + 5];
    const float* D1  = (const float*)d_in[base + 6];
    const float* db1 = (const float*)d_in[base + 7];
    const float* D2  = (const float*)d_in[base + 8];
    const float* db2 = (const float*)d_in[base + 9];
    const float* D3  = (const float*)d_in[base + 10];
    const float* db3 = (const float*)d_in[base + 11];
    float* out = (float*)d_out;

    __nv_bfloat16 *adjB, *bufAb;
    float *bufA, *bufB, *R, *G;
    cudaGetSymbolAddress((void**)&adjB, g_adjB);
    cudaGetSymbolAddress((void**)&bufAb, g_bufAb);
    cudaGetSymbolAddress((void**)&bufA, g_bufA);
    cudaGetSymbolAddress((void**)&bufB, g_bufB);
    cudaGetSymbolAddress((void**)&R, g_R);
    cudaGetSymbolAddress((void**)&G, g_G);

    static bool attr_set = false;
    if (!attr_set) {
        cudaFuncSetAttribute(big_gemm_bf16, cudaFuncAttributeMaxDynamicSharedMemorySize, BIG_SMEM);
        attr_set = true;
    }

    const dim3 blk(NTHREADS);
    const dim3 sgrd(HF / BN, NN / BM);    // (4, 64)
    const dim3 bgrd(HF / BBN, NN / BBM);  // (2, 64)

    // prep
    zero_all<<<(GRAPHS * NN + 255) / 256, 256>>>(R, G);
    segrow_conv<<<dim3(NN / 1024, NN / SR_CHUNK), 256>>>(adj, seg, adjB, R);

    // layer 1
    gemm_small<1><<<sgrd, blk>>>(X, W1, nullptr, bufAb, NN, HF, 256);
    big_gemm_bf16<<<bgrd, 256, BIG_SMEM>>>(adjB, bufAb, bufB, b1, 1);
    // layer 2
    gemm_small<1><<<sgrd, blk>>>(bufB, W2, nullptr, bufAb, NN, HF, HF);
    big_gemm_bf16<<<bgrd, 256, BIG_SMEM>>>(adjB, bufAb, bufB, b2, 1);
    // layer 3 folded: hW3 (fp32), then R @ hW3
    gemm_small<0><<<sgrd, blk>>>(bufB, W3, bufA, nullptr, NN, HF, HF);
    tiny_gemm<<<dim3(HF / 128, NN / 512), 256>>>(R, bufA, G);

    // tail
    mlp_tail<<<1, 1024>>>(G, seg, b3, D1, db1, D2, db2, D3, db3, out);
}

// round 11
// speedup vs baseline: 1.0668x; 1.0165x over previous
#include <cuda_runtime.h>
#include <cuda_bf16.h>
#include <cstdint>
#include <math.h>

// ---------------------------------------------------------------------------
// GCNGraph (sm_100, legacy mma.sync).
//   L1/L2: h = relu(adj @ (h@W) + b)   big GEMM bf16 m16n8k16 + ldmatrix
//   L3 folded: mean_s(adj@hW3+b3) = R@hW3/cnt+b3, fp32 path
//   MLP tail + sigmoid.
// R11: big GEMM 512 threads / 16 warps (warp tile 32x64) -> 4 warps/SMSP.
// ---------------------------------------------------------------------------

#define NN      8192
#define HF      512
#define GRAPHS  64

__device__ __nv_bfloat16 g_adjB[(size_t)NN * NN];  // bf16 adjacency (128MB)
__device__ __nv_bfloat16 g_bufAb[NN * HF];         // h@W bf16 (layers 1-2)
__device__ float g_bufA[NN * HF];                  // h@W3 fp32 (layer 3)
__device__ float g_bufB[NN * HF];                  // layer output h
__device__ float g_R[GRAPHS * NN];                 // segment rowsums of adj
__device__ float g_G[GRAPHS * HF];                 // segment sums layer-3

__device__ __forceinline__ uint32_t f2tf32(float x) {
    uint32_t r;
    asm("cvt.rna.tf32.f32 %0, %1;" : "=r"(r) : "f"(x));
    return r;
}
__device__ __forceinline__ uint32_t smem_u32(const void* p) {
    uint32_t a;
    asm("{ .reg .u64 t; cvta.to.shared.u64 t, %1; cvt.u32.u64 %0, t; }" : "=r"(a) : "l"(p));
    return a;
}

// ===================== bf16 big GEMM (adj @ hW) =============================
// C[8192,512] = Abf[8192,8192] @ Bbf[8192,512] (+bias, relu), fp32 accum.
// Tile 128x256x64, 16 warps (4m x 4n), warp tile 32x64, 3-stage cp.async.

#define NSTG 3
#define BBM 128
#define BBN 256
#define BBK 64
#define BTHREADS 512
#define A_RSTRIDE 144   // bytes per A smem row (128 data + 16 pad)
#define B_RSTRIDE 528   // bytes per B smem row (512 data + 16 pad)
#define A_BYTES (BBM * A_RSTRIDE)        // 18432
#define B_BYTES (BBK * B_RSTRIDE)        // 33792
#define STAGE_BYTES (A_BYTES + B_BYTES)  // 52224
#define BIG_SMEM (NSTG * STAGE_BYTES)    // 156672

__device__ __forceinline__ void ldmA(uint32_t a[4], uint32_t addr) {
    asm volatile("ldmatrix.sync.aligned.m8n8.x4.shared.b16 {%0,%1,%2,%3}, [%4];"
                 : "=r"(a[0]), "=r"(a[1]), "=r"(a[2]), "=r"(a[3]) : "r"(addr));
}
__device__ __forceinline__ void ldmB4(uint32_t b[4], uint32_t addr) {
    asm volatile("ldmatrix.sync.aligned.m8n8.x4.trans.shared.b16 {%0,%1,%2,%3}, [%4];"
                 : "=r"(b[0]), "=r"(b[1]), "=r"(b[2]), "=r"(b[3]) : "r"(addr));
}
__device__ __forceinline__ void mma_bf16(float* c, const uint32_t* a, const uint32_t* b) {
    asm volatile(
        "mma.sync.aligned.m16n8k16.row.col.f32.bf16.bf16.f32 "
        "{%0,%1,%2,%3}, {%4,%5,%6,%7}, {%8,%9}, {%0,%1,%2,%3};"
        : "+f"(c[0]), "+f"(c[1]), "+f"(c[2]), "+f"(c[3])
        : "r"(a[0]), "r"(a[1]), "r"(a[2]), "r"(a[3]), "r"(b[0]), "r"(b[1]));
}

__global__ void __launch_bounds__(BTHREADS, 1)
big_gemm_bf16(const __nv_bfloat16* __restrict__ A, const __nv_bfloat16* __restrict__ B,
              float* __restrict__ C, const float* __restrict__ bias, int relu)
{
    extern __shared__ char smem[];
    const uint32_t sbase = smem_u32(smem);

    const int tid  = threadIdx.x;
    const int warp = tid >> 5;
    const int lane = tid & 31;
    const int bm = blockIdx.y * BBM;
    const int bn = blockIdx.x * BBN;
    const int wm = (warp >> 2) * 32;       // 4 m-warps, warp tile 32 rows
    const int wn = (warp & 3) * 64;        // 4 n-warps, warp tile 64 cols
    const int g  = lane >> 2;
    const int q  = lane & 3;
    const int nk = NN / BBK;   // 128

    float acc[2][8][4];
    #pragma unroll
    for (int i = 0; i < 2; i++)
        #pragma unroll
        for (int j = 0; j < 8; j++)
            #pragma unroll
            for (int r = 0; r < 4; r++) acc[i][j][r] = 0.f;

    // cp.async: A 1024 chunks (2/thread), B 2048 chunks (4/thread), 16B each
    auto issue = [&](int slot, int k0) {
        const uint32_t ab = sbase + slot * STAGE_BYTES;
        const uint32_t bb = ab + A_BYTES;
        #pragma unroll
        for (int p = 0; p < 2; p++) {
            const int c = tid + BTHREADS * p;
            const int arow = c >> 3, ac = c & 7;            // 128 rows x 8 chunks
            asm volatile("cp.async.cg.shared.global [%0], [%1], 16;" ::
                "r"(ab + (uint32_t)(arow * A_RSTRIDE + ac * 16)),
                "l"(A + (size_t)(bm + arow) * NN + k0 + ac * 8));
        }
        #pragma unroll
        for (int p = 0; p < 4; p++) {
            const int c = tid + BTHREADS * p;
            const int brow = c >> 5, bc = c & 31;           // 64 rows x 32 chunks
            asm volatile("cp.async.cg.shared.global [%0], [%1], 16;" ::
                "r"(bb + (uint32_t)(brow * B_RSTRIDE + bc * 16)),
                "l"(B + (size_t)(k0 + brow) * HF + bn + bc * 8));
        }
        asm volatile("cp.async.commit_group;" ::: "memory");
    };

    issue(0, 0);
    issue(1, BBK);

    // ldmatrix lane-address components
    const int a_lrow = lane & 15;            // A: row within 16
    const int a_lkb  = (lane >> 4) * 8;      // A: k elem-block (0 or 8)
    const int b_m    = lane >> 3;            // B x4: matrix id 0..3
    const int b_krow = (b_m & 1) * 8 + (lane & 7);  // k row within 16
    const int b_ncol = (b_m >> 1) * 8;               // n sub-block (0 or 8)

    int slot = 0;
    for (int t = 0; t < nk; t++) {
        asm volatile("cp.async.wait_group 1;" ::: "memory");
        __syncthreads();
        if (t + 2 < nk) {
            int ns = slot + 2; if (ns >= NSTG) ns -= NSTG;
            issue(ns, (t + 2) * BBK);
        }

        const uint32_t ab = sbase + slot * STAGE_BYTES;
        const uint32_t bb = ab + A_BYTES;

        #pragma unroll
        for (int kk = 0; kk < BBK; kk += 16) {
            uint32_t af[2][4], bf[4][4];
            #pragma unroll
            for (int i = 0; i < 2; i++)
                ldmA(af[i], ab + (uint32_t)((wm + i * 16 + a_lrow) * A_RSTRIDE
                                            + (kk + a_lkb) * 2));
            #pragma unroll
            for (int j2 = 0; j2 < 4; j2++)
                ldmB4(bf[j2], bb + (uint32_t)((kk + b_krow) * B_RSTRIDE
                                              + (wn + j2 * 16 + b_ncol) * 2));
            #pragma unroll
            for (int i = 0; i < 2; i++)
                #pragma unroll
                for (int j2 = 0; j2 < 4; j2++) {
                    mma_bf16(acc[i][j2 * 2],     af[i], &bf[j2][0]);
                    mma_bf16(acc[i][j2 * 2 + 1], af[i], &bf[j2][2]);
                }
        }
        if (++slot >= NSTG) slot = 0;
    }

    // epilogue: bias + relu -> fp32 C
    #pragma unroll
    for (int i = 0; i < 2; i++) {
        #pragma unroll
        for (int j = 0; j < 8; j++) {
            const int row = bm + wm + i * 16 + g;
            const int col = bn + wn + j * 8 + 2 * q;
            const float bv0 = bias[col], bv1 = bias[col + 1];
            float v0 = acc[i][j][0] + bv0;
            float v1 = acc[i][j][1] + bv1;
            float v2 = acc[i][j][2] + bv0;
            float v3 = acc[i][j][3] + bv1;
            if (relu) {
                v0 = fmaxf(v0, 0.f); v1 = fmaxf(v1, 0.f);
                v2 = fmaxf(v2, 0.f); v3 = fmaxf(v3, 0.f);
            }
            *(float2*)(C + (size_t)row * HF + col)       = make_float2(v0, v1);
            *(float2*)(C + (size_t)(row + 8) * HF + col) = make_float2(v2, v3);
        }
    }
}

// ================== small SIMT tf32 GEMM (H @ W) ===========================
__device__ __forceinline__ void mma_frag(float* c, const uint32_t* a, const uint32_t* b) {
    asm volatile(
        "mma.sync.aligned.m16n8k8.row.col.f32.tf32.tf32.f32 "
        "{%0,%1,%2,%3}, {%4,%5,%6,%7}, {%8,%9}, {%0,%1,%2,%3};"
        : "+f"(c[0]), "+f"(c[1]), "+f"(c[2]), "+f"(c[3])
        : "r"(a[0]), "r"(a[1]), "r"(a[2]), "r"(a[3]), "r"(b[0]), "r"(b[1]));
}

#define BM 128
#define BN 128
#define BK 16
#define NTHREADS 256

template <int OUT_BF16>
__global__ void __launch_bounds__(NTHREADS)
gemm_small(const float* __restrict__ A, const float* __restrict__ B,
           float* __restrict__ Cf, __nv_bfloat16* __restrict__ Cb,
           int M, int N, int K)
{
    __shared__ uint32_t As[2][BM][BK + 4];
    __shared__ uint32_t Bs[2][BK][BN + 8];

    const int bm = blockIdx.y * BM;
    const int bn = blockIdx.x * BN;
    const int tid  = threadIdx.x;
    const int warp = tid >> 5;
    const int lane = tid & 31;
    const int wm = (warp >> 2) * 64;
    const int wn = (warp & 3) * 32;
    const int g  = lane >> 2;
    const int q  = lane & 3;

    float acc[4][4][4];
    #pragma unroll
    for (int i = 0; i < 4; i++)
        #pragma unroll
        for (int j = 0; j < 4; j++)
            #pragma unroll
            for (int r = 0; r < 4; r++) acc[i][j][r] = 0.f;

    const int arow = tid >> 2;
    const int acol = (tid & 3) * 4;
    const int brow = tid >> 5;
    const int bcol = (tid & 31) * 4;
    const int nk = K / BK;

    float4 ra0, ra1, rb0, rb1;
    ra0 = *(const float4*)(A + (size_t)(bm + arow) * K + acol);
    ra1 = *(const float4*)(A + (size_t)(bm + arow + 64) * K + acol);
    rb0 = *(const float4*)(B + (size_t)(brow) * N + bn + bcol);
    rb1 = *(const float4*)(B + (size_t)(brow + 8) * N + bn + bcol);
    {
        uint4 u;
        u.x = f2tf32(ra0.x); u.y = f2tf32(ra0.y); u.z = f2tf32(ra0.z); u.w = f2tf32(ra0.w);
        *(uint4*)&As[0][arow][acol] = u;
        u.x = f2tf32(ra1.x); u.y = f2tf32(ra1.y); u.z = f2tf32(ra1.z); u.w = f2tf32(ra1.w);
        *(uint4*)&As[0][arow + 64][acol] = u;
        u.x = f2tf32(rb0.x); u.y = f2tf32(rb0.y); u.z = f2tf32(rb0.z); u.w = f2tf32(rb0.w);
        *(uint4*)&Bs[0][brow][bcol] = u;
        u.x = f2tf32(rb1.x); u.y = f2tf32(rb1.y); u.z = f2tf32(rb1.z); u.w = f2tf32(rb1.w);
        *(uint4*)&Bs[0][brow + 8][bcol] = u;
    }
    __syncthreads();

    for (int t = 0; t < nk; t++) {
        const int cur = t & 1;
        const int nxt = cur ^ 1;
        const bool more = (t + 1 < nk);
        if (more) {
            const int k0 = (t + 1) * BK;
            ra0 = *(const float4*)(A + (size_t)(bm + arow) * K + k0 + acol);
            ra1 = *(const float4*)(A + (size_t)(bm + arow + 64) * K + k0 + acol);
            rb0 = *(const float4*)(B + (size_t)(k0 + brow) * N + bn + bcol);
            rb1 = *(const float4*)(B + (size_t)(k0 + brow + 8) * N + bn + bcol);
        }
        #pragma unroll
        for (int kk = 0; kk < BK; kk += 8) {
            uint32_t af[4][4], bf[4][2];
            #pragma unroll
            for (int i = 0; i < 4; i++) {
                const int r0 = wm + i * 16 + g;
                af[i][0] = As[cur][r0][kk + q];
                af[i][1] = As[cur][r0 + 8][kk + q];
                af[i][2] = As[cur][r0][kk + q + 4];
                af[i][3] = As[cur][r0 + 8][kk + q + 4];
            }
            #pragma unroll
            for (int j = 0; j < 4; j++) {
                const int c0 = wn + j * 8 + g;
                bf[j][0] = Bs[cur][kk + q][c0];
                bf[j][1] = Bs[cur][kk + q + 4][c0];
            }
            #pragma unroll
            for (int i = 0; i < 4; i++)
                #pragma unroll
                for (int j = 0; j < 4; j++)
                    mma_frag(acc[i][j], af[i], bf[j]);
        }
        if (more) {
            uint4 u;
            u.x = f2tf32(ra0.x); u.y = f2tf32(ra0.y); u.z = f2tf32(ra0.z); u.w = f2tf32(ra0.w);
            *(uint4*)&As[nxt][arow][acol] = u;
            u.x = f2tf32(ra1.x); u.y = f2tf32(ra1.y); u.z = f2tf32(ra1.z); u.w = f2tf32(ra1.w);
            *(uint4*)&As[nxt][arow + 64][acol] = u;
            u.x = f2tf32(rb0.x); u.y = f2tf32(rb0.y); u.z = f2tf32(rb0.z); u.w = f2tf32(rb0.w);
            *(uint4*)&Bs[nxt][brow][bcol] = u;
            u.x = f2tf32(rb1.x); u.y = f2tf32(rb1.y); u.z = f2tf32(rb1.z); u.w = f2tf32(rb1.w);
            *(uint4*)&Bs[nxt][brow + 8][bcol] = u;
        }
        __syncthreads();
    }

    #pragma unroll
    for (int i = 0; i < 4; i++) {
        #pragma unroll
        for (int j = 0; j < 4; j++) {
            const int row = bm + wm + i * 16 + g;
            const int col = bn + wn + j * 8 + 2 * q;
            if (OUT_BF16) {
                *(__nv_bfloat162*)(Cb + (size_t)row * N + col) =
                    __floats2bfloat162_rn(acc[i][j][0], acc[i][j][1]);
                *(__nv_bfloat162*)(Cb + (size_t)(row + 8) * N + col) =
                    __floats2bfloat162_rn(acc[i][j][2], acc[i][j][3]);
            } else {
                *(float2*)(Cf + (size_t)row * N + col) =
                    make_float2(acc[i][j][0], acc[i][j][1]);
                *(float2*)(Cf + (size_t)(row + 8) * N + col) =
                    make_float2(acc[i][j][2], acc[i][j][3]);
            }
        }
    }
}

// =============================== helpers ====================================

// Fused: adjB = bf16(adj) AND R[s][col] += segment rowsums (fp32).
#define SR_CHUNK 256

__global__ void __launch_bounds__(256)
segrow_conv(const float* __restrict__ adj, const int* __restrict__ seg,
            __nv_bfloat16* __restrict__ adjB, float* __restrict__ R)
{
    const int col = (blockIdx.x * 256 + threadIdx.x) * 4;
    const int r0  = blockIdx.y * SR_CHUNK;
    const int r1  = r0 + SR_CHUNK;

    float4 acc = make_float4(0.f, 0.f, 0.f, 0.f);
    int cur = seg[r0];

    #pragma unroll 4
    for (int i = r0; i < r1; i++) {
        const int s = __ldg(&seg[i]);
        if (s != cur) {
            atomicAdd(&R[(size_t)cur * NN + col],     acc.x);
            atomicAdd(&R[(size_t)cur * NN + col + 1], acc.y);
            atomicAdd(&R[(size_t)cur * NN + col + 2], acc.z);
            atomicAdd(&R[(size_t)cur * NN + col + 3], acc.w);
            acc = make_float4(0.f, 0.f, 0.f, 0.f);
            cur = s;
        }
        const float4 v = *(const float4*)(adj + (size_t)i * NN + col);
        acc.x += v.x; acc.y += v.y; acc.z += v.z; acc.w += v.w;
        __nv_bfloat162 o01 = __floats2bfloat162_rn(v.x, v.y);
        __nv_bfloat162 o23 = __floats2bfloat162_rn(v.z, v.w);
        uint2 o;
        o.x = *(uint32_t*)&o01;
        o.y = *(uint32_t*)&o23;
        *(uint2*)(adjB + (size_t)i * NN + col) = o;
    }
    atomicAdd(&R[(size_t)cur * NN + col],     acc.x);
    atomicAdd(&R[(size_t)cur * NN + col + 1], acc.y);
    atomicAdd(&R[(size_t)cur * NN + col + 2], acc.z);
    atomicAdd(&R[(size_t)cur * NN + col + 3], acc.w);
}

// one launch zeroes both R and G
__global__ void zero_all(float* __restrict__ R, float* __restrict__ G) {
    const int i = blockIdx.x * blockDim.x + threadIdx.x;
    if (i < GRAPHS * NN) R[i] = 0.f;
    if (i < GRAPHS * HF) G[i] = 0.f;
}

// G[64,512] += R[64,8192] @ H[8192,512]  (fp32 SIMT, k-split with atomics)
__global__ void __launch_bounds__(256)
tiny_gemm(const float* __restrict__ R, const float* __restrict__ H,
          float* __restrict__ G)
{
    __shared__ float sA[64][33];
    __shared__ float sB[32][132];
    const int tid = threadIdx.x;
    const int bn = blockIdx.x * 128;
    const int k0 = blockIdx.y * 512;
    const int row0 = (tid >> 5) * 8;
    const int col0 = (tid & 31) * 4;

    float acc[8][4];
    #pragma unroll
    for (int r = 0; r < 8; r++)
        #pragma unroll
        for (int c = 0; c < 4; c++) acc[r][c] = 0.f;

    for (int kt = 0; kt < 512; kt += 32) {
        const int k = k0 + kt;
        #pragma unroll
        for (int i = 0; i < 8; i++) {
            const int e = tid + 256 * i;
            sA[e >> 5][e & 31] = R[(size_t)(e >> 5) * NN + k + (e & 31)];
        }
        #pragma unroll
        for (int i = 0; i < 16; i++) {
            const int e = tid + 256 * i;
            sB[e >> 7][e & 127] = H[(size_t)(k + (e >> 7)) * HF + bn + (e & 127)];
        }
        __syncthreads();
        #pragma unroll
        for (int kk = 0; kk < 32; kk++) {
            const float4 b4 = *(const float4*)&sB[kk][col0];
            #pragma unroll
            for (int r = 0; r < 8; r++) {
                const float a = sA[row0 + r][kk];
                acc[r][0] += a * b4.x;
                acc[r][1] += a * b4.y;
                acc[r][2] += a * b4.z;
                acc[r][3] += a * b4.w;
            }
        }
        __syncthreads();
    }
    #pragma unroll
    for (int r = 0; r < 8; r++)
        #pragma unroll
        for (int c = 0; c < 4; c++)
            atomicAdd(&G[(row0 + r) * HF + bn + col0 + c], acc[r][c]);
}

// mean + b3 + MLP (512->16->8->1) + sigmoid. one block, 1024 threads.
__global__ void mlp_tail(const float* __restrict__ G, const int* __restrict__ seg,
                         const float* __restrict__ b3,
                         const float* __restrict__ D1, const float* __restrict__ db1,
                         const float* __restrict__ D2, const float* __restrict__ db2,
                         const float* __restrict__ D3, const float* __restrict__ db3,
                         float* __restrict__ out)
{
    __shared__ int   cnt[GRAPHS];
    __shared__ float s1[GRAPHS][16];
    __shared__ float s2[GRAPHS][8];
    const int tid = threadIdx.x;

    if (tid < GRAPHS) cnt[tid] = 0;
    __syncthreads();
    for (int n = tid; n < NN; n += 1024) atomicAdd(&cnt[seg[n]], 1);
    __syncthreads();

    {
        const int gph = tid >> 4, j = tid & 15;
        const float inv = 1.f / (float)max(cnt[gph], 1);
        float acc = 0.f;
        const float* grow = G + gph * HF;
        for (int k = 0; k < HF; k++)
            acc += (grow[k] * inv + b3[k]) * D1[k * 16 + j];
        s1[gph][j] = fmaxf(acc + db1[j], 0.f);
    }
    __syncthreads();
    if (tid < 512) {
        const int gph = tid >> 3, j = tid & 7;
        float acc = 0.f;
        for (int k = 0; k < 16; k++) acc += s1[gph][k] * D2[k * 8 + j];
        s2[gph][j] = fmaxf(acc + db2[j], 0.f);
    }
    __syncthreads();
    if (tid < GRAPHS) {
        float acc = 0.f;
        for (int k = 0; k < 8; k++) acc += s2[tid][k] * D3[k];
        out[tid] = 1.f / (1.f + expf(-(acc + db3[0])));
    }
}

// ================================= host =====================================

extern "C" void kernel_launch(void* const* d_in, const int* in_sizes, int n_in,
                              void* d_out, int out_size)
{
    const float* X   = (const float*)d_in[0];
    const float* adj = (const float*)d_in[1];
    const int*   seg = (const int*)d_in[2];
    const int base = n_in - 12;
    const float* W1  = (const float*)d_in[base + 0];
    const float* b1  = (const float*)d_in[base + 1];
    const float* W2  = (const float*)d_in[base + 2];
    const float* b2  = (const float*)d_in[base + 3];
    const float* W3  = (const float*)d_in[base + 4];
    const float* b3  = (const float*)d_in[base + 5];
    const float* D1  = (const float*)d_in[base + 6];
    const float* db1 = (const float*)d_in[base + 7];
    const float* D2  = (const float*)d_in[base + 8];
    const float* db2 = (const float*)d_in[base + 9];
    const float* D3  = (const float*)d_in[base + 10];
    const float* db3 = (const float*)d_in[base + 11];
    float* out = (float*)d_out;

    __nv_bfloat16 *adjB, *bufAb;
    float *bufA, *bufB, *R, *G;
    cudaGetSymbolAddress((void**)&adjB, g_adjB);
    cudaGetSymbolAddress((void**)&bufAb, g_bufAb);
    cudaGetSymbolAddress((void**)&bufA, g_bufA);
    cudaGetSymbolAddress((void**)&bufB, g_bufB);
    cudaGetSymbolAddress((void**)&R, g_R);
    cudaGetSymbolAddress((void**)&G, g_G);

    static bool attr_set = false;
    if (!attr_set) {
        cudaFuncSetAttribute(big_gemm_bf16, cudaFuncAttributeMaxDynamicSharedMemorySize, BIG_SMEM);
        attr_set = true;
    }

    const dim3 blk(NTHREADS);
    const dim3 sgrd(HF / BN, NN / BM);    // (4, 64)
    const dim3 bgrd(HF / BBN, NN / BBM);  // (2, 64)

    // prep
    zero_all<<<(GRAPHS * NN + 255) / 256, 256>>>(R, G);
    segrow_conv<<<dim3(NN / 1024, NN / SR_CHUNK), 256>>>(adj, seg, adjB, R);

    // layer 1
    gemm_small<1><<<sgrd, blk>>>(X, W1, nullptr, bufAb, NN, HF, 256);
    big_gemm_bf16<<<bgrd, BTHREADS, BIG_SMEM>>>(adjB, bufAb, bufB, b1, 1);
    // layer 2
    gemm_small<1><<<sgrd, blk>>>(bufB, W2, nullptr, bufAb, NN, HF, HF);
    big_gemm_bf16<<<bgrd, BTHREADS, BIG_SMEM>>>(adjB, bufAb, bufB, b2, 1);
    // layer 3 folded: hW3 (fp32), then R @ hW3
    gemm_small<0><<<sgrd, blk>>>(bufB, W3, bufA, nullptr, NN, HF, HF);
    tiny_gemm<<<dim3(HF / 128, NN / 512), 256>>>(R, bufA, G);

    // tail
    mlp_tail<<<1, 1024>>>(G, seg, b3, D1, db1, D2, db2, D3, db3, out);
}